// round 10
// baseline (speedup 1.0000x reference)
#include <cuda_runtime.h>
#include <cstdint>

// K1: per-(quarter,type,graph) CTA streams 1/4 of a graph's rows -> partial SUM in g_part (16 MB).
// K2: tiled GEMM: mean = (p0+p1+p2+p3)/cnt stored pre-duplicated as f32x2,
//     [16,128]@[128,256]+bias, W staged in smem 16-k chunks, packed f32x2 FMA.
//
// Inputs: 0:x_a 1:W_a 2:b_a 3:x_b 4:W_b 5:b_b 6:ptr_a 7:ptr_b
// Output: [4096, 512] f32 (cols 0..255 type a, 256..511 type b)

#define NGRAPH 4096
#define D_IN   128
#define D_OUT  256
#define TM     16    // graphs per GEMM tile

// layout: plane (q*2 + t), then graph, then col
__device__ float g_part[8 * NGRAPH * D_IN];   // 16 MB scratch

// ---------------- Kernel 1: quarter-graph partial sums ----------------
__global__ __launch_bounds__(128, 8)
void seg_sum_kernel(const float* __restrict__ x_a, const float* __restrict__ x_b,
                    const int* __restrict__ ptr_a, const int* __restrict__ ptr_b)
{
    const int bid = blockIdx.x;               // 0..32767
    const int q   = bid >> 13;                // quarter 0..3
    const int t   = (bid >> 12) & 1;          // type
    const int g   = bid & (NGRAPH - 1);

    const float* __restrict__ x   = t ? x_b   : x_a;
    const int*   __restrict__ ptr = t ? ptr_b : ptr_a;

    const int tid = threadIdx.x;              // 128 = 4 warps
    const int w   = tid >> 5;
    const int c4  = tid & 31;

    const int r0  = ptr[g];
    const int r1  = ptr[g + 1];
    const int len = r1 - r0;
    const int rs  = r0 + (int)(((long long)len * q)       >> 2);
    const int re  = r0 + (int)(((long long)len * (q + 1)) >> 2);

    const float4* __restrict__ x4 = reinterpret_cast<const float4*>(x);

    float4 a0 = make_float4(0.f,0.f,0.f,0.f);
    float4 a1 = make_float4(0.f,0.f,0.f,0.f);
    float4 a2 = make_float4(0.f,0.f,0.f,0.f);
    float4 a3 = make_float4(0.f,0.f,0.f,0.f);

    int i = rs + w;                           // 4 rows in flight per warp
    for (; i + 12 < re; i += 16) {
        float4 v0 = __ldg(&x4[(size_t)i        * 32 + c4]);
        float4 v1 = __ldg(&x4[(size_t)(i + 4)  * 32 + c4]);
        float4 v2 = __ldg(&x4[(size_t)(i + 8)  * 32 + c4]);
        float4 v3 = __ldg(&x4[(size_t)(i + 12) * 32 + c4]);
        a0.x += v0.x; a0.y += v0.y; a0.z += v0.z; a0.w += v0.w;
        a1.x += v1.x; a1.y += v1.y; a1.z += v1.z; a1.w += v1.w;
        a2.x += v2.x; a2.y += v2.y; a2.z += v2.z; a2.w += v2.w;
        a3.x += v3.x; a3.y += v3.y; a3.z += v3.z; a3.w += v3.w;
    }
    for (; i < re; i += 4) {
        float4 v0 = __ldg(&x4[(size_t)i * 32 + c4]);
        a0.x += v0.x; a0.y += v0.y; a0.z += v0.z; a0.w += v0.w;
    }
    a0.x += a1.x + a2.x + a3.x;
    a0.y += a1.y + a2.y + a3.y;
    a0.z += a1.z + a2.z + a3.z;
    a0.w += a1.w + a2.w + a3.w;

    __shared__ float red[4][D_IN];
    red[w][c4 * 4 + 0] = a0.x;
    red[w][c4 * 4 + 1] = a0.y;
    red[w][c4 * 4 + 2] = a0.z;
    red[w][c4 * 4 + 3] = a0.w;
    __syncthreads();

    float s = red[0][tid] + red[1][tid] + red[2][tid] + red[3][tid];
    g_part[(((size_t)q * 2 + t) * NGRAPH + g) * D_IN + tid] = s;
}

// ---------------- Kernel 2: combine + GEMM + bias ----------------
__global__ __launch_bounds__(256, 4)
void gemm_kernel(const float* __restrict__ W_a, const float* __restrict__ b_a,
                 const float* __restrict__ W_b, const float* __restrict__ b_b,
                 const int* __restrict__ ptr_a, const int* __restrict__ ptr_b,
                 float* __restrict__ out)
{
    const int t  = blockIdx.y;
    const int g0 = blockIdx.x * TM;

    const float* __restrict__ W    = t ? W_b   : W_a;
    const float* __restrict__ bias = t ? b_b   : b_a;
    const int*   __restrict__ ptr  = t ? ptr_b : ptr_a;

    __shared__ float2 meanD[TM][D_IN];     // 16 KB, each entry {m, m} pre-duplicated
    __shared__ float  WS[16][D_OUT];       // 16 KB (one 16-k chunk of W)
    __shared__ float  invc[TM];

    const int tid = threadIdx.x;           // 256 = 64 x 4
    const int tx  = tid & 63;              // cols [4*tx, 4*tx+4)
    const int ty  = tid >> 6;              // graphs ty*4 .. ty*4+3

    if (tid < TM) {
        int m = g0 + tid;
        int c = ptr[m + 1] - ptr[m];
        invc[tid] = (c > 0) ? 1.f / (float)c : 0.f;
    }
    __syncthreads();

    // combine 4 quarter-partials -> duplicated mean tile
    // 16x128 = 2048 floats = 512 float4, 2 per thread
    {
        const size_t base = ((size_t)t * NGRAPH + g0) * D_IN;
        const float4* p0 = reinterpret_cast<const float4*>(g_part + base);
        const float4* p1 = reinterpret_cast<const float4*>(g_part + base + (size_t)2 * NGRAPH * D_IN);
        const float4* p2 = reinterpret_cast<const float4*>(g_part + base + (size_t)4 * NGRAPH * D_IN);
        const float4* p3 = reinterpret_cast<const float4*>(g_part + base + (size_t)6 * NGRAPH * D_IN);
        #pragma unroll
        for (int j = 0; j < 2; j++) {
            int i4  = tid + 256 * j;       // float4 index
            int row = i4 >> 5;             // 32 float4 per row
            int c0  = (i4 & 31) * 4;
            float4 u = p0[i4], v = p1[i4], w2 = p2[i4], z = p3[i4];
            float  r = invc[row];
            float mx = (u.x + v.x + w2.x + z.x) * r;
            float my = (u.y + v.y + w2.y + z.y) * r;
            float mz = (u.z + v.z + w2.z + z.z) * r;
            float mw = (u.w + v.w + w2.w + z.w) * r;
            meanD[row][c0 + 0] = make_float2(mx, mx);
            meanD[row][c0 + 1] = make_float2(my, my);
            meanD[row][c0 + 2] = make_float2(mz, mz);
            meanD[row][c0 + 3] = make_float2(mw, mw);
        }
    }

    unsigned long long acc[4][2];          // 4 graphs x 4 cols as 2x f32x2
    #pragma unroll
    for (int i = 0; i < 4; i++) { acc[i][0] = 0ull; acc[i][1] = 0ull; }

    const float4* W4 = reinterpret_cast<const float4*>(W);

    #pragma unroll 1
    for (int kc = 0; kc < 8; kc++) {
        __syncthreads();                   // protect WS (and meanD fill on kc=0)
        float4* ws4 = reinterpret_cast<float4*>(&WS[0][0]);
        #pragma unroll
        for (int j = 0; j < 4; j++)
            ws4[tid + 256 * j] = __ldg(&W4[kc * 1024 + tid + 256 * j]);
        __syncthreads();

        #pragma unroll
        for (int k = 0; k < 16; k++) {
            ulonglong2 wp = *reinterpret_cast<const ulonglong2*>(&WS[k][4 * tx]);
            #pragma unroll
            for (int i = 0; i < 4; i++) {
                // pre-duplicated broadcast operand: single LDS.64, no pack mov
                unsigned long long mm =
                    *reinterpret_cast<const unsigned long long*>(&meanD[ty * 4 + i][kc * 16 + k]);
                asm("fma.rn.f32x2 %0, %1, %2, %0;" : "+l"(acc[i][0]) : "l"(mm), "l"(wp.x));
                asm("fma.rn.f32x2 %0, %1, %2, %0;" : "+l"(acc[i][1]) : "l"(mm), "l"(wp.y));
            }
        }
    }

    const float4 bv = __ldg(reinterpret_cast<const float4*>(bias) + tx);
    float4* out4 = reinterpret_cast<float4*>(out);

    #pragma unroll
    for (int i = 0; i < 4; i++) {
        const int ml = ty * 4 + i;
        const int m  = g0 + ml;
        float4 o;
        asm("mov.b64 {%0, %1}, %2;" : "=f"(o.x), "=f"(o.y) : "l"(acc[i][0]));
        asm("mov.b64 {%0, %1}, %2;" : "=f"(o.z), "=f"(o.w) : "l"(acc[i][1]));
        if (invc[ml] > 0.f) {
            o.x += bv.x; o.y += bv.y; o.z += bv.z; o.w += bv.w;
        } else {
            o = make_float4(0.f, 0.f, 0.f, 0.f);
        }
        out4[(size_t)m * 128 + t * 64 + tx] = o;
    }
}

extern "C" void kernel_launch(void* const* d_in, const int* in_sizes, int n_in,
                              void* d_out, int out_size)
{
    const float* x_a   = (const float*)d_in[0];
    const float* W_a   = (const float*)d_in[1];
    const float* b_a   = (const float*)d_in[2];
    const float* x_b   = (const float*)d_in[3];
    const float* W_b   = (const float*)d_in[4];
    const float* b_b   = (const float*)d_in[5];
    const int*   ptr_a = (const int*)d_in[6];
    const int*   ptr_b = (const int*)d_in[7];
    float* out = (float*)d_out;

    seg_sum_kernel<<<8 * NGRAPH, 128>>>(x_a, x_b, ptr_a, ptr_b);

    dim3 gridB(NGRAPH / TM, 2);
    gemm_kernel<<<gridB, 256>>>(W_a, b_a, W_b, b_b, ptr_a, ptr_b, out);
}

// round 11
// speedup vs baseline: 1.0475x; 1.0475x over previous
#include <cuda_runtime.h>
#include <cstdint>

// K1: per-(half,type,graph) CTA streams half a graph's rows -> partial SUM in g_part (8 MB).
//     (R9 proven config; x loads use .cs streaming hint — zero-reuse data, evict first.)
// K2: register-blocked outer-product GEMM: mean=(p0+p1)/cnt stored k-major duplicated f32x2,
//     16(M)x256(N) CTA tile, 4x8 thread tile, packed f32x2 FMA, ~1 B/MAC smem traffic.
//
// Inputs: 0:x_a 1:W_a 2:b_a 3:x_b 4:W_b 5:b_b 6:ptr_a 7:ptr_b
// Output: [4096, 512] f32 (cols 0..255 type a, 256..511 type b)

#define NGRAPH 4096
#define D_IN   128
#define D_OUT  256
#define TM     16    // graphs per GEMM tile

// layout: plane (h*2 + t), then graph, then col
__device__ float g_part[4 * NGRAPH * D_IN];   // 8 MB scratch

// ---------------- Kernel 1: half-graph partial sums ----------------
__global__ __launch_bounds__(128, 8)
void seg_sum_kernel(const float* __restrict__ x_a, const float* __restrict__ x_b,
                    const int* __restrict__ ptr_a, const int* __restrict__ ptr_b)
{
    const int bid = blockIdx.x;               // 0..16383
    const int h   = bid >> 13;                // half
    const int t   = (bid >> 12) & 1;          // type
    const int g   = bid & (NGRAPH - 1);

    const float* __restrict__ x   = t ? x_b   : x_a;
    const int*   __restrict__ ptr = t ? ptr_b : ptr_a;

    const int tid = threadIdx.x;              // 128 = 4 warps
    const int w   = tid >> 5;
    const int c4  = tid & 31;

    const int r0  = ptr[g];
    const int r1  = ptr[g + 1];
    const int mid = r0 + ((r1 - r0) >> 1);
    const int rs  = h ? mid : r0;
    const int re  = h ? r1  : mid;

    const float4* __restrict__ x4 = reinterpret_cast<const float4*>(x);

    float4 a0 = make_float4(0.f,0.f,0.f,0.f);
    float4 a1 = make_float4(0.f,0.f,0.f,0.f);

    int i = rs + w;                           // warps stride 4 rows, unroll 2
    for (; i + 4 < re; i += 8) {
        float4 v0 = __ldcs(&x4[(size_t)i * 32 + c4]);
        float4 v1 = __ldcs(&x4[(size_t)(i + 4) * 32 + c4]);
        a0.x += v0.x; a0.y += v0.y; a0.z += v0.z; a0.w += v0.w;
        a1.x += v1.x; a1.y += v1.y; a1.z += v1.z; a1.w += v1.w;
    }
    if (i < re) {
        float4 v0 = __ldcs(&x4[(size_t)i * 32 + c4]);
        a0.x += v0.x; a0.y += v0.y; a0.z += v0.z; a0.w += v0.w;
    }
    a0.x += a1.x; a0.y += a1.y; a0.z += a1.z; a0.w += a1.w;

    __shared__ float red[4][D_IN];
    red[w][c4 * 4 + 0] = a0.x;
    red[w][c4 * 4 + 1] = a0.y;
    red[w][c4 * 4 + 2] = a0.z;
    red[w][c4 * 4 + 3] = a0.w;
    __syncthreads();

    float s = red[0][tid] + red[1][tid] + red[2][tid] + red[3][tid];
    g_part[(((size_t)h * 2 + t) * NGRAPH + g) * D_IN + tid] = s;
}

// ---------------- Kernel 2: combine + register-blocked GEMM + bias ----------------
__global__ __launch_bounds__(128, 4)
void gemm_kernel(const float* __restrict__ W_a, const float* __restrict__ b_a,
                 const float* __restrict__ W_b, const float* __restrict__ b_b,
                 const int* __restrict__ ptr_a, const int* __restrict__ ptr_b,
                 float* __restrict__ out)
{
    const int t  = blockIdx.y;
    const int g0 = blockIdx.x * TM;

    const float* __restrict__ W    = t ? W_b   : W_a;
    const float* __restrict__ bias = t ? b_b   : b_a;
    const int*   __restrict__ ptr  = t ? ptr_b : ptr_a;

    __shared__ float2 aTD[D_IN][TM];       // 16 KB: [k][m] mean, duplicated {v,v}
    __shared__ float  WS[16][D_OUT];       // 16 KB: one 16-k chunk of W
    __shared__ float  invc[TM];

    const int tid = threadIdx.x;           // 128 = 4 warps
    const int tx  = tid & 31;              // N cols [8*tx, 8*tx+8)
    const int ty  = tid >> 5;              // M rows [4*ty, 4*ty+4)

    if (tid < TM) {
        int m = g0 + tid;
        int c = ptr[m + 1] - ptr[m];
        invc[tid] = (c > 0) ? 1.f / (float)c : 0.f;
    }
    __syncthreads();

    // combine halves -> k-major duplicated mean tile.
    // 16 rows x 128 k = 512 float4 reads, 4 per thread (coalesced).
    {
        const size_t base = ((size_t)t * NGRAPH + g0) * D_IN;
        const float4* p0 = reinterpret_cast<const float4*>(g_part + base);
        const float4* p1 = reinterpret_cast<const float4*>(g_part + base + (size_t)2 * NGRAPH * D_IN);
        #pragma unroll
        for (int j = 0; j < 4; j++) {
            int i4  = tid + 128 * j;       // float4 index: row = i4>>5, k = (i4&31)*4
            int row = i4 >> 5;
            int kb  = (i4 & 31) * 4;
            float4 u = p0[i4], v = p1[i4];
            float  r = invc[row];
            float m0 = (u.x + v.x) * r;
            float m1 = (u.y + v.y) * r;
            float m2 = (u.z + v.z) * r;
            float m3 = (u.w + v.w) * r;
            aTD[kb + 0][row] = make_float2(m0, m0);
            aTD[kb + 1][row] = make_float2(m1, m1);
            aTD[kb + 2][row] = make_float2(m2, m2);
            aTD[kb + 3][row] = make_float2(m3, m3);
        }
    }

    unsigned long long acc[4][4];          // [mi][n-pair]: 4 rows x 8 cols
    #pragma unroll
    for (int i = 0; i < 4; i++)
        #pragma unroll
        for (int j = 0; j < 4; j++) acc[i][j] = 0ull;

    const float4* W4 = reinterpret_cast<const float4*>(W);

    #pragma unroll 1
    for (int kc = 0; kc < 8; kc++) {
        __syncthreads();                   // protect WS (and aTD fill on kc=0)
        {
            float4* ws4 = reinterpret_cast<float4*>(&WS[0][0]);
            #pragma unroll
            for (int j = 0; j < 8; j++)
                ws4[tid + 128 * j] = __ldg(&W4[kc * 1024 + tid + 128 * j]);
        }
        __syncthreads();

        #pragma unroll
        for (int k = 0; k < 16; k++) {
            // B frag: 8 cols = 2x LDS.128
            ulonglong2 b0 = *reinterpret_cast<const ulonglong2*>(&WS[k][8 * tx]);
            ulonglong2 b1 = *reinterpret_cast<const ulonglong2*>(&WS[k][8 * tx + 4]);
            // A frag: 4 duplicated rows = 2x LDS.128 (warp-uniform -> broadcast)
            ulonglong2 a0 = *reinterpret_cast<const ulonglong2*>(&aTD[kc * 16 + k][4 * ty]);
            ulonglong2 a1 = *reinterpret_cast<const ulonglong2*>(&aTD[kc * 16 + k][4 * ty + 2]);

            asm("fma.rn.f32x2 %0, %1, %2, %0;" : "+l"(acc[0][0]) : "l"(a0.x), "l"(b0.x));
            asm("fma.rn.f32x2 %0, %1, %2, %0;" : "+l"(acc[0][1]) : "l"(a0.x), "l"(b0.y));
            asm("fma.rn.f32x2 %0, %1, %2, %0;" : "+l"(acc[0][2]) : "l"(a0.x), "l"(b1.x));
            asm("fma.rn.f32x2 %0, %1, %2, %0;" : "+l"(acc[0][3]) : "l"(a0.x), "l"(b1.y));
            asm("fma.rn.f32x2 %0, %1, %2, %0;" : "+l"(acc[1][0]) : "l"(a0.y), "l"(b0.x));
            asm("fma.rn.f32x2 %0, %1, %2, %0;" : "+l"(acc[1][1]) : "l"(a0.y), "l"(b0.y));
            asm("fma.rn.f32x2 %0, %1, %2, %0;" : "+l"(acc[1][2]) : "l"(a0.y), "l"(b1.x));
            asm("fma.rn.f32x2 %0, %1, %2, %0;" : "+l"(acc[1][3]) : "l"(a0.y), "l"(b1.y));
            asm("fma.rn.f32x2 %0, %1, %2, %0;" : "+l"(acc[2][0]) : "l"(a1.x), "l"(b0.x));
            asm("fma.rn.f32x2 %0, %1, %2, %0;" : "+l"(acc[2][1]) : "l"(a1.x), "l"(b0.y));
            asm("fma.rn.f32x2 %0, %1, %2, %0;" : "+l"(acc[2][2]) : "l"(a1.x), "l"(b1.x));
            asm("fma.rn.f32x2 %0, %1, %2, %0;" : "+l"(acc[2][3]) : "l"(a1.x), "l"(b1.y));
            asm("fma.rn.f32x2 %0, %1, %2, %0;" : "+l"(acc[3][0]) : "l"(a1.y), "l"(b0.x));
            asm("fma.rn.f32x2 %0, %1, %2, %0;" : "+l"(acc[3][1]) : "l"(a1.y), "l"(b0.y));
            asm("fma.rn.f32x2 %0, %1, %2, %0;" : "+l"(acc[3][2]) : "l"(a1.y), "l"(b1.x));
            asm("fma.rn.f32x2 %0, %1, %2, %0;" : "+l"(acc[3][3]) : "l"(a1.y), "l"(b1.y));
        }
    }

    // epilogue: bias + empty-graph mask, 2x float4 store per row
    const float4 bv0 = __ldg(reinterpret_cast<const float4*>(bias) + 2 * tx);
    const float4 bv1 = __ldg(reinterpret_cast<const float4*>(bias) + 2 * tx + 1);
    float4* out4 = reinterpret_cast<float4*>(out);

    #pragma unroll
    for (int i = 0; i < 4; i++) {
        const int ml = 4 * ty + i;
        const int m  = g0 + ml;
        float4 o0, o1;
        asm("mov.b64 {%0, %1}, %2;" : "=f"(o0.x), "=f"(o0.y) : "l"(acc[i][0]));
        asm("mov.b64 {%0, %1}, %2;" : "=f"(o0.z), "=f"(o0.w) : "l"(acc[i][1]));
        asm("mov.b64 {%0, %1}, %2;" : "=f"(o1.x), "=f"(o1.y) : "l"(acc[i][2]));
        asm("mov.b64 {%0, %1}, %2;" : "=f"(o1.z), "=f"(o1.w) : "l"(acc[i][3]));
        if (invc[ml] > 0.f) {
            o0.x += bv0.x; o0.y += bv0.y; o0.z += bv0.z; o0.w += bv0.w;
            o1.x += bv1.x; o1.y += bv1.y; o1.z += bv1.z; o1.w += bv1.w;
        } else {
            o0 = make_float4(0.f, 0.f, 0.f, 0.f);
            o1 = make_float4(0.f, 0.f, 0.f, 0.f);
        }
        // out row m, cols t*256 + 8*tx
        out4[(size_t)m * 128 + t * 64 + 2 * tx]     = o0;
        out4[(size_t)m * 128 + t * 64 + 2 * tx + 1] = o1;
    }
}

extern "C" void kernel_launch(void* const* d_in, const int* in_sizes, int n_in,
                              void* d_out, int out_size)
{
    const float* x_a   = (const float*)d_in[0];
    const float* W_a   = (const float*)d_in[1];
    const float* b_a   = (const float*)d_in[2];
    const float* x_b   = (const float*)d_in[3];
    const float* W_b   = (const float*)d_in[4];
    const float* b_b   = (const float*)d_in[5];
    const int*   ptr_a = (const int*)d_in[6];
    const int*   ptr_b = (const int*)d_in[7];
    float* out = (float*)d_out;

    seg_sum_kernel<<<4 * NGRAPH, 128>>>(x_a, x_b, ptr_a, ptr_b);

    dim3 gridB(NGRAPH / TM, 2);
    gemm_kernel<<<gridB, 128>>>(W_a, b_a, W_b, b_b, ptr_a, ptr_b, out);
}

// round 12
// speedup vs baseline: 1.1369x; 1.0854x over previous
#include <cuda_runtime.h>
#include <cstdint>

// K1: per-(half,type,graph) CTA streams half a graph's rows -> partial SUM in g_part (8 MB).
//     __ldcs streaming loads (zero reuse), 4-deep float4 MLP per warp.
// K2: combine -> transposed duplicated mean aTD[k][g]={m,m} in smem; register-blocked
//     outer product 8(M)x4(N) per thread, W streamed via LDG.128 (L1-resident),
//     zero barriers in main loop, 16 FFMA2 per 576B conflict-free traffic.
//
// Inputs: 0:x_a 1:W_a 2:b_a 3:x_b 4:W_b 5:b_b 6:ptr_a 7:ptr_b
// Output: [4096, 512] f32 (cols 0..255 type a, 256..511 type b)

#define NGRAPH 4096
#define D_IN   128
#define D_OUT  256
#define TM     32    // graphs per GEMM tile

// layout: plane (h*2 + t), then graph, then col
__device__ float g_part[4 * NGRAPH * D_IN];   // 8 MB scratch

// ---------------- Kernel 1: half-graph partial sums ----------------
__global__ __launch_bounds__(128, 8)
void seg_sum_kernel(const float* __restrict__ x_a, const float* __restrict__ x_b,
                    const int* __restrict__ ptr_a, const int* __restrict__ ptr_b)
{
    const int bid = blockIdx.x;               // 0..16383
    const int h   = bid >> 13;                // half
    const int t   = (bid >> 12) & 1;          // type
    const int g   = bid & (NGRAPH - 1);

    const float* __restrict__ x   = t ? x_b   : x_a;
    const int*   __restrict__ ptr = t ? ptr_b : ptr_a;

    const int tid = threadIdx.x;              // 128 = 4 warps
    const int w   = tid >> 5;
    const int c4  = tid & 31;

    const int r0  = ptr[g];
    const int r1  = ptr[g + 1];
    const int mid = r0 + ((r1 - r0) >> 1);
    const int rs  = h ? mid : r0;
    const int re  = h ? r1  : mid;

    const float4* __restrict__ x4 = reinterpret_cast<const float4*>(x);

    float4 a0 = make_float4(0.f,0.f,0.f,0.f);
    float4 a1 = make_float4(0.f,0.f,0.f,0.f);
    float4 a2 = make_float4(0.f,0.f,0.f,0.f);
    float4 a3 = make_float4(0.f,0.f,0.f,0.f);

    int i = rs + w;                           // 4 rows in flight per warp
    for (; i + 12 < re; i += 16) {
        float4 v0 = __ldcs(&x4[(size_t)i        * 32 + c4]);
        float4 v1 = __ldcs(&x4[(size_t)(i + 4)  * 32 + c4]);
        float4 v2 = __ldcs(&x4[(size_t)(i + 8)  * 32 + c4]);
        float4 v3 = __ldcs(&x4[(size_t)(i + 12) * 32 + c4]);
        a0.x += v0.x; a0.y += v0.y; a0.z += v0.z; a0.w += v0.w;
        a1.x += v1.x; a1.y += v1.y; a1.z += v1.z; a1.w += v1.w;
        a2.x += v2.x; a2.y += v2.y; a2.z += v2.z; a2.w += v2.w;
        a3.x += v3.x; a3.y += v3.y; a3.z += v3.z; a3.w += v3.w;
    }
    for (; i < re; i += 4) {
        float4 v0 = __ldcs(&x4[(size_t)i * 32 + c4]);
        a0.x += v0.x; a0.y += v0.y; a0.z += v0.z; a0.w += v0.w;
    }
    a0.x += a1.x + a2.x + a3.x;
    a0.y += a1.y + a2.y + a3.y;
    a0.z += a1.z + a2.z + a3.z;
    a0.w += a1.w + a2.w + a3.w;

    __shared__ float red[4][D_IN];
    red[w][c4 * 4 + 0] = a0.x;
    red[w][c4 * 4 + 1] = a0.y;
    red[w][c4 * 4 + 2] = a0.z;
    red[w][c4 * 4 + 3] = a0.w;
    __syncthreads();

    float s = red[0][tid] + red[1][tid] + red[2][tid] + red[3][tid];
    g_part[(((size_t)h * 2 + t) * NGRAPH + g) * D_IN + tid] = s;
}

// ---------------- Kernel 2: combine + register-blocked GEMM + bias ----------------
#define APAD 34   // row stride (float2) for aTD: even -> 16B-aligned rows

__global__ __launch_bounds__(256, 2)
void gemm_kernel(const float* __restrict__ W_a, const float* __restrict__ b_a,
                 const float* __restrict__ W_b, const float* __restrict__ b_b,
                 const int* __restrict__ ptr_a, const int* __restrict__ ptr_b,
                 float* __restrict__ out)
{
    const int t  = blockIdx.y;
    const int g0 = blockIdx.x * TM;

    const float* __restrict__ W    = t ? W_b   : W_a;
    const float* __restrict__ bias = t ? b_b   : b_a;
    const int*   __restrict__ ptr  = t ? ptr_b : ptr_a;

    __shared__ float2 aTD[D_IN][APAD];     // [k][graph] mean, duplicated {v,v}; ~34.8 KB
    __shared__ float  invc[TM];

    const int tid  = threadIdx.x;          // 256 = 8 warps
    const int lane = tid & 31;
    const int warp = tid >> 5;
    const int gg   = warp >> 1;            // graph group 0..3 -> graphs [8*gg, 8*gg+8)
    const int ch   = warp & 1;             // column half: cols [128*ch + 4*lane)
    const int colq = ch * 32 + lane;       // float4 column index 0..63

    if (tid < TM) {
        int m = g0 + tid;
        int c = ptr[m + 1] - ptr[m];
        invc[tid] = (c > 0) ? 1.f / (float)c : 0.f;
    }
    __syncthreads();

    // combine halves -> transposed duplicated mean tile.
    // 32 rows x 32 float4 = 1024 float4, 4 per thread (coalesced reads).
    {
        const float4* p0 = reinterpret_cast<const float4*>(g_part) + ((size_t)t * NGRAPH + g0) * 32;
        const float4* p1 = p0 + (size_t)2 * NGRAPH * 32;
        #pragma unroll
        for (int j = 0; j < 4; j++) {
            int i4  = tid + 256 * j;       // row = i4>>5 (graph), k4 = i4&31
            int row = i4 >> 5;
            int k4  = i4 & 31;
            float4 u = p0[row * 32 + k4];
            float4 v = p1[row * 32 + k4];
            float  r = invc[row];
            float m0 = (u.x + v.x) * r;
            float m1 = (u.y + v.y) * r;
            float m2 = (u.z + v.z) * r;
            float m3 = (u.w + v.w) * r;
            aTD[4 * k4 + 0][row] = make_float2(m0, m0);
            aTD[4 * k4 + 1][row] = make_float2(m1, m1);
            aTD[4 * k4 + 2][row] = make_float2(m2, m2);
            aTD[4 * k4 + 3][row] = make_float2(m3, m3);
        }
    }
    __syncthreads();

    unsigned long long acc[8][2];          // [graph][col-pair]
    #pragma unroll
    for (int i = 0; i < 8; i++) { acc[i][0] = 0ull; acc[i][1] = 0ull; }

    const ulonglong2* __restrict__ Wd = reinterpret_cast<const ulonglong2*>(W);

    #pragma unroll 2
    for (int kk = 0; kk < D_IN; kk++) {
        // B frag: 4 cols via one LDG.128 (16B lane stride, coalesced, L1-resident W)
        ulonglong2 b = __ldg(&Wd[kk * 64 + colq]);
        // A frag: 8 duplicated graphs, warp-uniform -> broadcast LDS.128 x4
        const float2* ap = &aTD[kk][8 * gg];
        ulonglong2 a01 = *reinterpret_cast<const ulonglong2*>(ap + 0);
        ulonglong2 a23 = *reinterpret_cast<const ulonglong2*>(ap + 2);
        ulonglong2 a45 = *reinterpret_cast<const ulonglong2*>(ap + 4);
        ulonglong2 a67 = *reinterpret_cast<const ulonglong2*>(ap + 6);

        asm("fma.rn.f32x2 %0, %1, %2, %0;" : "+l"(acc[0][0]) : "l"(a01.x), "l"(b.x));
        asm("fma.rn.f32x2 %0, %1, %2, %0;" : "+l"(acc[0][1]) : "l"(a01.x), "l"(b.y));
        asm("fma.rn.f32x2 %0, %1, %2, %0;" : "+l"(acc[1][0]) : "l"(a01.y), "l"(b.x));
        asm("fma.rn.f32x2 %0, %1, %2, %0;" : "+l"(acc[1][1]) : "l"(a01.y), "l"(b.y));
        asm("fma.rn.f32x2 %0, %1, %2, %0;" : "+l"(acc[2][0]) : "l"(a23.x), "l"(b.x));
        asm("fma.rn.f32x2 %0, %1, %2, %0;" : "+l"(acc[2][1]) : "l"(a23.x), "l"(b.y));
        asm("fma.rn.f32x2 %0, %1, %2, %0;" : "+l"(acc[3][0]) : "l"(a23.y), "l"(b.x));
        asm("fma.rn.f32x2 %0, %1, %2, %0;" : "+l"(acc[3][1]) : "l"(a23.y), "l"(b.y));
        asm("fma.rn.f32x2 %0, %1, %2, %0;" : "+l"(acc[4][0]) : "l"(a45.x), "l"(b.x));
        asm("fma.rn.f32x2 %0, %1, %2, %0;" : "+l"(acc[4][1]) : "l"(a45.x), "l"(b.y));
        asm("fma.rn.f32x2 %0, %1, %2, %0;" : "+l"(acc[5][0]) : "l"(a45.y), "l"(b.x));
        asm("fma.rn.f32x2 %0, %1, %2, %0;" : "+l"(acc[5][1]) : "l"(a45.y), "l"(b.y));
        asm("fma.rn.f32x2 %0, %1, %2, %0;" : "+l"(acc[6][0]) : "l"(a67.x), "l"(b.x));
        asm("fma.rn.f32x2 %0, %1, %2, %0;" : "+l"(acc[6][1]) : "l"(a67.x), "l"(b.y));
        asm("fma.rn.f32x2 %0, %1, %2, %0;" : "+l"(acc[7][0]) : "l"(a67.y), "l"(b.x));
        asm("fma.rn.f32x2 %0, %1, %2, %0;" : "+l"(acc[7][1]) : "l"(a67.y), "l"(b.y));
    }

    // epilogue: bias + empty-graph mask
    const float4 bv = __ldg(reinterpret_cast<const float4*>(bias) + colq);
    float4* out4 = reinterpret_cast<float4*>(out);

    #pragma unroll
    for (int i = 0; i < 8; i++) {
        const int ml = 8 * gg + i;
        const int m  = g0 + ml;
        float4 o;
        asm("mov.b64 {%0, %1}, %2;" : "=f"(o.x), "=f"(o.y) : "l"(acc[i][0]));
        asm("mov.b64 {%0, %1}, %2;" : "=f"(o.z), "=f"(o.w) : "l"(acc[i][1]));
        if (invc[ml] > 0.f) {
            o.x += bv.x; o.y += bv.y; o.z += bv.z; o.w += bv.w;
        } else {
            o = make_float4(0.f, 0.f, 0.f, 0.f);
        }
        // out row m, float4 col t*64 + colq
        out4[(size_t)m * 128 + t * 64 + colq] = o;
    }
}

extern "C" void kernel_launch(void* const* d_in, const int* in_sizes, int n_in,
                              void* d_out, int out_size)
{
    const float* x_a   = (const float*)d_in[0];
    const float* W_a   = (const float*)d_in[1];
    const float* b_a   = (const float*)d_in[2];
    const float* x_b   = (const float*)d_in[3];
    const float* W_b   = (const float*)d_in[4];
    const float* b_b   = (const float*)d_in[5];
    const int*   ptr_a = (const int*)d_in[6];
    const int*   ptr_b = (const int*)d_in[7];
    float* out = (float*)d_out;

    seg_sum_kernel<<<4 * NGRAPH, 128>>>(x_a, x_b, ptr_a, ptr_b);

    dim3 gridB(NGRAPH / TM, 2);
    gemm_kernel<<<gridB, 256>>>(W_a, b_a, W_b, b_b, ptr_a, ptr_b, out);
}